// round 12
// baseline (speedup 1.0000x reference)
#include <cuda_runtime.h>
#include <cuda_bf16.h>

#define NN 65536
#define EE 1048576
#define DD 64
#define CC 101
#define BN_EPS 1e-5f

// ---------------- scratch (device globals; no allocation allowed) -------------
__device__ float g_Y0[NN * DD];        // single-tensor gather input
__device__ float g_Z [NN * 2 * DD];    // dual-tensor interleaved gather input
__device__ float g_A0[NN * DD];
__device__ float g_A1[NN * DD];
__device__ float g_H1[NN * DD];
__device__ float g_H2[NN * DD];
__device__ float g_H3[NN * DD];
__device__ int    g_cnt[NN];
__device__ int    g_ptr[NN + 1];
__device__ int    g_esrc[EE];
__device__ double g_stat[3][128];   // per-conv: [0:64) col sums, [64:128) col sumsq

// ---------------- CSR build --------------------------------------------------
__global__ void k_init() {
    int i = blockIdx.x * blockDim.x + threadIdx.x;
    if (i < NN) g_cnt[i] = 0;
    if (i < 3 * 128) ((double*)g_stat)[i] = 0.0;
}

__global__ void k_count(const int* __restrict__ dst) {
    int e = (blockIdx.x * blockDim.x + threadIdx.x) * 2;
    if (e < EE) {
        int2 d = *(const int2*)(dst + e);
        atomicAdd(&g_cnt[d.x], 1);
        atomicAdd(&g_cnt[d.y], 1);
    }
}

__global__ void k_scan() {
    __shared__ int ps[1024];
    int t = threadIdx.x;
    int base = t << 6;
    int s = 0;
#pragma unroll 8
    for (int j = 0; j < 64; j++) s += g_cnt[base + j];
    ps[t] = s;
    __syncthreads();
    for (int off = 1; off < 1024; off <<= 1) {
        int add = 0;
        if (t >= off) add = ps[t - off];
        __syncthreads();
        ps[t] += add;
        __syncthreads();
    }
    int incl = ps[t];
    int run = incl - s;
#pragma unroll 8
    for (int j = 0; j < 64; j++) {
        int c = g_cnt[base + j];
        g_ptr[base + j] = run;
        run += c;
        g_cnt[base + j] = 0;   // reuse as fill cursor in scatter
    }
    if (t == 1023) g_ptr[NN] = incl;
}

__global__ void k_scatter(const int* __restrict__ src, const int* __restrict__ dst) {
    int e = (blockIdx.x * blockDim.x + threadIdx.x) * 2;
    if (e < EE) {
        int2 d = *(const int2*)(dst + e);
        int2 s = *(const int2*)(src + e);
        int p0 = atomicAdd(&g_cnt[d.x], 1);
        g_esrc[g_ptr[d.x] + p0] = s.x;
        int p1 = atomicAdd(&g_cnt[d.y], 1);
        g_esrc[g_ptr[d.y] + p1] = s.y;
    }
}

// ---------------- register-tiled GEMM: 128 rows x 64 cols per block ----------
// 256 threads: tx = t&15 -> 4 cols, ty = t>>4 -> 8 rows. 32 outputs/thread.
// DUAL: two weight sets, one input tile, interleaved float4 output (Z layout:
// Z4[row*32 + 2tx+j] = {w0col(4tx+2j), w0col(4tx+2j+1), w1col(4tx+2j), w1col(4tx+2j+1)}).
// IN_BN: BN+ReLU applied to input on load (stats from g_stat[statIn] + gvec/bvec).
// STATS: accumulate column sum/sumsq of output0 into g_stat[statOut].
#define MM_AS_STRIDE 66
#define MM_SMEM_FLOATS (128 * MM_AS_STRIDE + 2 * 64 * 64 + 64 + 64 + 64 + 64)

template <int DUAL, int IN_BN, int STATS>
__global__ __launch_bounds__(256) void k_mm(
        const float* __restrict__ in,
        const float* __restrict__ W0, const float* __restrict__ W1,
        float* __restrict__ out0,
        const float* __restrict__ gvec, const float* __restrict__ bvec,
        int statIn, int statOut) {
    extern __shared__ float sm[];
    float* As  = sm;                          // 128 x 66
    float* Ws  = As + 128 * MM_AS_STRIDE;     // [2][64][64]
    float* bnS = Ws + 2 * 64 * 64;            // 64
    float* bnB = bnS + 64;                    // 64
    float* ssum = bnB + 64;                   // 64
    float* ssq  = ssum + 64;                  // 64

    int t = threadIdx.x;
    int tx = t & 15, ty = t >> 4;
    int row0 = blockIdx.x * 128;

    // weights
    for (int i = t; i < 4096; i += 256) {
        Ws[i] = W0[i];
        if (DUAL) Ws[4096 + i] = W1[i];
    }
    // BN scale/shift
    if (IN_BN && t < 64) {
        double sum = g_stat[statIn][t];
        double sq  = g_stat[statIn][64 + t];
        double mu_d = sum / (double)NN;
        double var_d = sq / (double)NN - mu_d * mu_d;
        float inv = rsqrtf(fmaxf((float)var_d, 0.f) + BN_EPS);
        float sc = inv * gvec[t];
        bnS[t] = sc;
        bnB[t] = bvec[t] - (float)mu_d * sc;
    }
    if (STATS && t < 64) { ssum[t] = 0.f; ssq[t] = 0.f; }
    if (IN_BN) __syncthreads();   // bnS/bnB ready before A-tile transform

    // A tile (128 x 64), optionally BN+ReLU on load
    {
        const float4* inr = (const float4*)(in + (size_t)row0 * 64);
#pragma unroll
        for (int i = 0; i < 8; i++) {
            int l = i * 256 + t;
            float4 v = inr[l];
            int r = l >> 4;
            int kk = (l & 15) * 4;
            if (IN_BN) {
                v.x = fmaxf(fmaf(v.x, bnS[kk + 0], bnB[kk + 0]), 0.f);
                v.y = fmaxf(fmaf(v.y, bnS[kk + 1], bnB[kk + 1]), 0.f);
                v.z = fmaxf(fmaf(v.z, bnS[kk + 2], bnB[kk + 2]), 0.f);
                v.w = fmaxf(fmaf(v.w, bnS[kk + 3], bnB[kk + 3]), 0.f);
            }
            float* d = As + r * MM_AS_STRIDE + kk;
            d[0] = v.x; d[1] = v.y; d[2] = v.z; d[3] = v.w;
        }
    }
    __syncthreads();

    float acc0[8][4];
    float acc1[8][4];
#pragma unroll
    for (int i = 0; i < 8; i++)
#pragma unroll
        for (int j = 0; j < 4; j++) { acc0[i][j] = 0.f; if (DUAL) acc1[i][j] = 0.f; }

    const float* arow = As + ty * 8 * MM_AS_STRIDE;
#pragma unroll 4
    for (int k = 0; k < 64; k++) {
        float4 w0 = *(const float4*)(Ws + k * 64 + tx * 4);
        float4 w1;
        if (DUAL) w1 = *(const float4*)(Ws + 4096 + k * 64 + tx * 4);
#pragma unroll
        for (int i = 0; i < 8; i++) {
            float a = arow[i * MM_AS_STRIDE + k];
            acc0[i][0] = fmaf(a, w0.x, acc0[i][0]);
            acc0[i][1] = fmaf(a, w0.y, acc0[i][1]);
            acc0[i][2] = fmaf(a, w0.z, acc0[i][2]);
            acc0[i][3] = fmaf(a, w0.w, acc0[i][3]);
            if (DUAL) {
                acc1[i][0] = fmaf(a, w1.x, acc1[i][0]);
                acc1[i][1] = fmaf(a, w1.y, acc1[i][1]);
                acc1[i][2] = fmaf(a, w1.z, acc1[i][2]);
                acc1[i][3] = fmaf(a, w1.w, acc1[i][3]);
            }
        }
    }

    // store
#pragma unroll
    for (int i = 0; i < 8; i++) {
        int row = row0 + ty * 8 + i;
        if (DUAL) {
            ((float4*)out0)[row * 32 + 2 * tx + 0] =
                make_float4(acc0[i][0], acc0[i][1], acc1[i][0], acc1[i][1]);
            ((float4*)out0)[row * 32 + 2 * tx + 1] =
                make_float4(acc0[i][2], acc0[i][3], acc1[i][2], acc1[i][3]);
        } else {
            ((float4*)out0)[row * 16 + tx] =
                make_float4(acc0[i][0], acc0[i][1], acc0[i][2], acc0[i][3]);
        }
    }

    if (STATS) {
        float cs[4] = {0.f, 0.f, 0.f, 0.f}, cq[4] = {0.f, 0.f, 0.f, 0.f};
#pragma unroll
        for (int i = 0; i < 8; i++)
#pragma unroll
            for (int j = 0; j < 4; j++) {
                float v = acc0[i][j];
                cs[j] += v;
                cq[j] += v * v;
            }
#pragma unroll
        for (int j = 0; j < 4; j++) {
            atomicAdd(&ssum[tx * 4 + j], cs[j]);
            atomicAdd(&ssq[tx * 4 + j], cq[j]);
        }
        __syncthreads();
        if (t < 64) {
            atomicAdd(&g_stat[statOut][t],      (double)ssum[t]);
            atomicAdd(&g_stat[statOut][64 + t], (double)ssq[t]);
        }
    }
}

// ---------------- gather-max: 4 warps per node, software-pipelined -----------
// 256 threads = 8 warps = 2 nodes/block. Warp wsub handles edges b+wsub, +4, ...
// HAS_S: single tensor (float2/lane from Y). HAS_D: dual tensor (float4/lane
// from interleaved Z). Partial maxima combined via smem.
template <int HAS_S, int HAS_D>
__global__ __launch_bounds__(256) void k_gath(
        const float* __restrict__ yS, const float* __restrict__ zD,
        const float* __restrict__ pos,
        const float* __restrict__ WpS,   // pos-rows (2x64) of single Wl
        const float* __restrict__ WpD0, const float* __restrict__ WpD1,
        float* __restrict__ aS,
        float* __restrict__ aD0, float* __restrict__ aD1) {
    __shared__ float2 redS[2][4][32];
    __shared__ float4 redD[2][4][32];

    int t = threadIdx.x;
    int warp = t >> 5, lane = t & 31;
    int nodeLocal = warp >> 2;
    int wsub = warp & 3;
    int node = blockIdx.x * 2 + nodeLocal;

    const float2* YS = (const float2*)yS;
    const float4* ZD = (const float4*)zD;
    const float2* P  = (const float2*)pos;

    float2 wxS, wyS, wxD0, wyD0, wxD1, wyD1;
    if (HAS_S) {
        wxS = ((const float2*)WpS)[lane];
        wyS = ((const float2*)(WpS + 64))[lane];
    }
    if (HAS_D) {
        wxD0 = ((const float2*)WpD0)[lane];
        wyD0 = ((const float2*)(WpD0 + 64))[lane];
        wxD1 = ((const float2*)WpD1)[lane];
        wyD1 = ((const float2*)(WpD1 + 64))[lane];
    }

    float2 pi = P[node];
    const float NEG = -3.402823466e38f;
    float2 mS = make_float2(NEG, NEG);
    float4 mD = make_float4(NEG, NEG, NEG, NEG);
    if (wsub == 0) {   // self-loop (dpos = 0)
        if (HAS_S) mS = YS[node * 32 + lane];
        if (HAS_D) mD = ZD[node * 32 + lane];
    }

    int b = g_ptr[node], e = g_ptr[node + 1];
    int k = b + wsub;
    // 2-stage software pipeline: indices/pos/features of edge i+1 issue before
    // the compute on edge i.
    int s0 = (k < e) ? g_esrc[k] : 0;
    float2 ps0 = P[s0];
    float2 vS0; float4 vD0;
    if (HAS_S) vS0 = YS[s0 * 32 + lane];
    if (HAS_D) vD0 = ZD[s0 * 32 + lane];

    while (k < e) {
        int kn = k + 4;
        int sn = (kn < e) ? g_esrc[kn] : 0;
        float2 psn = P[sn];
        float2 vSn; float4 vDn;
        if (HAS_S) vSn = YS[sn * 32 + lane];
        if (HAS_D) vDn = ZD[sn * 32 + lane];

        float dx = ps0.x - pi.x, dy = ps0.y - pi.y;
        if (HAS_S) {
            float a = fmaf(dx, wxS.x, fmaf(dy, wyS.x, vS0.x));
            float c = fmaf(dx, wxS.y, fmaf(dy, wyS.y, vS0.y));
            mS.x = fmaxf(mS.x, a);
            mS.y = fmaxf(mS.y, c);
        }
        if (HAS_D) {
            float a = fmaf(dx, wxD0.x, fmaf(dy, wyD0.x, vD0.x));
            float c = fmaf(dx, wxD0.y, fmaf(dy, wyD0.y, vD0.y));
            float d2 = fmaf(dx, wxD1.x, fmaf(dy, wyD1.x, vD0.z));
            float f = fmaf(dx, wxD1.y, fmaf(dy, wyD1.y, vD0.w));
            mD.x = fmaxf(mD.x, a);
            mD.y = fmaxf(mD.y, c);
            mD.z = fmaxf(mD.z, d2);
            mD.w = fmaxf(mD.w, f);
        }
        k = kn; s0 = sn; ps0 = psn;
        if (HAS_S) vS0 = vSn;
        if (HAS_D) vD0 = vDn;
    }

    if (HAS_S) redS[nodeLocal][wsub][lane] = mS;
    if (HAS_D) redD[nodeLocal][wsub][lane] = mD;
    __syncthreads();

    if (wsub == 0) {
        if (HAS_S) {
            float2 a = redS[nodeLocal][0][lane], b2 = redS[nodeLocal][1][lane];
            float2 c = redS[nodeLocal][2][lane], d = redS[nodeLocal][3][lane];
            float2 r;
            r.x = fmaxf(fmaxf(a.x, b2.x), fmaxf(c.x, d.x));
            r.y = fmaxf(fmaxf(a.y, b2.y), fmaxf(c.y, d.y));
            ((float2*)aS)[node * 32 + lane] = r;
        }
        if (HAS_D) {
            float4 a = redD[nodeLocal][0][lane], b2 = redD[nodeLocal][1][lane];
            float4 c = redD[nodeLocal][2][lane], d = redD[nodeLocal][3][lane];
            float2 r0, r1;
            r0.x = fmaxf(fmaxf(a.x, b2.x), fmaxf(c.x, d.x));
            r0.y = fmaxf(fmaxf(a.y, b2.y), fmaxf(c.y, d.y));
            r1.x = fmaxf(fmaxf(a.z, b2.z), fmaxf(c.z, d.z));
            r1.y = fmaxf(fmaxf(a.w, b2.w), fmaxf(c.w, d.w));
            ((float2*)aD0)[node * 32 + lane] = r0;
            ((float2*)aD1)[node * 32 + lane] = r1;
        }
    }
}

// ---------------- cls head: 128 rows x 101 cols, register tiled --------------
#define HD_SMEM_FLOATS (128 * MM_AS_STRIDE + 64 * 128 + 128)

__global__ __launch_bounds__(512) void k_head101(
        const float* __restrict__ in, const float* __restrict__ W,
        const float* __restrict__ bias, float* __restrict__ out) {
    extern __shared__ float sm[];
    float* As = sm;                        // 128 x 66
    float* Ws = As + 128 * MM_AS_STRIDE;   // 64 x 128 (zero-padded)
    float* bS = Ws + 64 * 128;             // 128

    int t = threadIdx.x;
    int tx = t & 31, ty = t >> 5;
    int row0 = blockIdx.x * 128;

    for (int i = t; i < 64 * 128; i += 512) {
        int k = i >> 7, c = i & 127;
        Ws[i] = (c < CC) ? W[k * CC + c] : 0.f;
    }
    if (t < 128) bS[t] = (t < CC) ? bias[t] : 0.f;

    {
        const float4* inr = (const float4*)(in + (size_t)row0 * 64);
#pragma unroll
        for (int i = 0; i < 4; i++) {
            int l = i * 512 + t;
            float4 v = inr[l];
            int r = l >> 4;
            int kk = (l & 15) * 4;
            float* d = As + r * MM_AS_STRIDE + kk;
            d[0] = v.x; d[1] = v.y; d[2] = v.z; d[3] = v.w;
        }
    }
    __syncthreads();

    float acc[8][4];
#pragma unroll
    for (int i = 0; i < 8; i++)
#pragma unroll
        for (int j = 0; j < 4; j++) acc[i][j] = 0.f;

    const float* arow = As + ty * 8 * MM_AS_STRIDE;
#pragma unroll 4
    for (int k = 0; k < 64; k++) {
        float4 w = *(const float4*)(Ws + k * 128 + tx * 4);
#pragma unroll
        for (int i = 0; i < 8; i++) {
            float a = arow[i * MM_AS_STRIDE + k];
            acc[i][0] = fmaf(a, w.x, acc[i][0]);
            acc[i][1] = fmaf(a, w.y, acc[i][1]);
            acc[i][2] = fmaf(a, w.z, acc[i][2]);
            acc[i][3] = fmaf(a, w.w, acc[i][3]);
        }
    }

#pragma unroll
    for (int i = 0; i < 8; i++) {
        int row = row0 + ty * 8 + i;
#pragma unroll
        for (int j = 0; j < 4; j++) {
            int col = tx * 4 + j;
            if (col < CC) out[(size_t)row * CC + col] = acc[i][j] + bS[col];
        }
    }
}

// ---------------- small head GEMM (K = 4, 1): warp per row, shuffle ----------
template <int K>
__global__ void k_head(const float* __restrict__ in, const float* __restrict__ W,
                       const float* __restrict__ bias, float* __restrict__ out) {
    __shared__ float Ws[64 * K];
    int t = threadIdx.x;
    for (int i = t; i < 64 * K; i += blockDim.x) Ws[i] = W[i];
    __syncthreads();
    int warp = t >> 5, lane = t & 31;
    int row = blockIdx.x * 8 + warp;
    constexpr int NC = (K + 31) / 32;
    float acc[NC];
#pragma unroll
    for (int c = 0; c < NC; c++) {
        int col = lane + 32 * c;
        acc[c] = (col < K) ? bias[col] : 0.f;
    }
    float r0v = in[row * 64 + lane];
    float r1v = in[row * 64 + 32 + lane];
#pragma unroll
    for (int j = 0; j < 32; j++) {
        float v = __shfl_sync(0xffffffffu, r0v, j);
#pragma unroll
        for (int c = 0; c < NC; c++) {
            int col = lane + 32 * c;
            if (col < K) acc[c] = fmaf(v, Ws[j * K + col], acc[c]);
        }
    }
#pragma unroll
    for (int j = 0; j < 32; j++) {
        float v = __shfl_sync(0xffffffffu, r1v, j);
#pragma unroll
        for (int c = 0; c < NC; c++) {
            int col = lane + 32 * c;
            if (col < K) acc[c] = fmaf(v, Ws[(32 + j) * K + col], acc[c]);
        }
    }
#pragma unroll
    for (int c = 0; c < NC; c++) {
        int col = lane + 32 * c;
        if (col < K) out[row * K + col] = acc[c];
    }
}

// ---------------- launch -----------------------------------------------------
extern "C" void kernel_launch(void* const* d_in, const int* in_sizes, int n_in,
                              void* d_out, int out_size) {
    const float* x   = (const float*)d_in[0];
    const float* pos = (const float*)d_in[1];
    const int*   ei  = (const int*)  d_in[2];
    const float* W11 = (const float*)d_in[3];
    const float* W12 = (const float*)d_in[4];
    const float* g1  = (const float*)d_in[5];
    const float* b1  = (const float*)d_in[6];
    const float* W21 = (const float*)d_in[7];
    const float* W22 = (const float*)d_in[8];
    const float* g2  = (const float*)d_in[9];
    const float* b2  = (const float*)d_in[10];
    const float* W31 = (const float*)d_in[11];
    const float* W32 = (const float*)d_in[12];
    const float* g3  = (const float*)d_in[13];
    const float* b3  = (const float*)d_in[14];
    const float* Wr1 = (const float*)d_in[15];
    const float* Wr2 = (const float*)d_in[16];
    const float* br2 = (const float*)d_in[17];
    const float* Wc1 = (const float*)d_in[18];
    const float* Wc2 = (const float*)d_in[19];
    const float* bc2 = (const float*)d_in[20];
    const float* Wo1 = (const float*)d_in[21];
    const float* Wo2 = (const float*)d_in[22];
    const float* bo2 = (const float*)d_in[23];
    float* out = (float*)d_out;

    float* out_cls = out;                      // N x 101
    float* out_reg = out + (size_t)NN * CC;    // N x 4
    float* out_obj = out_reg + (size_t)NN * 4; // N x 1

    const int* src = ei;
    const int* dst = ei + EE;

    float *Y0, *Z, *A0, *A1, *H1, *H2, *H3;
    cudaGetSymbolAddress((void**)&Y0, g_Y0);
    cudaGetSymbolAddress((void**)&Z,  g_Z);
    cudaGetSymbolAddress((void**)&A0, g_A0);
    cudaGetSymbolAddress((void**)&A1, g_A1);
    cudaGetSymbolAddress((void**)&H1, g_H1);
    cudaGetSymbolAddress((void**)&H2, g_H2);
    cudaGetSymbolAddress((void**)&H3, g_H3);

    const int MM_SMEM = MM_SMEM_FLOATS * 4;
    const int HD_SMEM = HD_SMEM_FLOATS * 4;
    cudaFuncSetAttribute(k_mm<0, 0, 0>, cudaFuncAttributeMaxDynamicSharedMemorySize, MM_SMEM);
    cudaFuncSetAttribute(k_mm<0, 0, 1>, cudaFuncAttributeMaxDynamicSharedMemorySize, MM_SMEM);
    cudaFuncSetAttribute(k_mm<0, 1, 0>, cudaFuncAttributeMaxDynamicSharedMemorySize, MM_SMEM);
    cudaFuncSetAttribute(k_mm<1, 1, 0>, cudaFuncAttributeMaxDynamicSharedMemorySize, MM_SMEM);
    cudaFuncSetAttribute(k_head101,     cudaFuncAttributeMaxDynamicSharedMemorySize, HD_SMEM);

    const int TB = 256;

    // ---- CSR build
    k_init<<<(NN + TB - 1) / TB, TB>>>();
    k_count<<<EE / (2 * TB), TB>>>(dst);
    k_scan<<<1, 1024>>>();
    k_scatter<<<EE / (2 * TB), TB>>>(src, dst);

    const int GM = NN / 128;    // k_mm / k_head101 grid
    const int GA = NN / 2;      // gather grid (2 nodes/block)
    const int GH = NN / 8;      // small-head grid

    // ---- conv1: x -> H1 (stats0)
    k_mm<0, 0, 0><<<GM, TB, MM_SMEM>>>(x, W11, nullptr, Y0, nullptr, nullptr, 0, 0);
    k_gath<1, 0><<<GA, TB>>>(Y0, nullptr, pos, W11 + 64 * 64, nullptr, nullptr,
                             A0, nullptr, nullptr);
    k_mm<0, 0, 1><<<GM, TB, MM_SMEM>>>(A0, W12, nullptr, H1, nullptr, nullptr, 0, 0);

    // ---- conv2 + conv3 lin from relu(bn1(H1)), dual interleaved -> Z
    k_mm<1, 1, 0><<<GM, TB, MM_SMEM>>>(H1, W21, W31, Z, g1, b1, 0, 0);
    k_gath<0, 1><<<GA, TB>>>(nullptr, Z, pos, nullptr, W21 + 64 * 64, W31 + 64 * 64,
                             nullptr, A0, A1);
    k_mm<0, 0, 1><<<GM, TB, MM_SMEM>>>(A0, W22, nullptr, H2, nullptr, nullptr, 0, 1);
    k_mm<0, 0, 1><<<GM, TB, MM_SMEM>>>(A1, W32, nullptr, H3, nullptr, nullptr, 0, 2);

    // ---- head pre-lins: reg from relu(bn2(H2)) -> Y0 ; cls+obj from relu(bn3(H3)) -> Z
    k_mm<0, 1, 0><<<GM, TB, MM_SMEM>>>(H2, Wr1, nullptr, Y0, g2, b2, 1, 0);
    k_mm<1, 1, 0><<<GM, TB, MM_SMEM>>>(H3, Wc1, Wo1, Z, g3, b3, 2, 0);

    // ---- single triple gather: reg (Y0) + cls/obj (Z)
    k_gath<1, 1><<<GA, TB>>>(Y0, Z, pos, Wr1 + 64 * 64, Wc1 + 64 * 64, Wo1 + 64 * 64,
                             A0, A1, H1);

    // ---- output heads
    k_head<4><<<GH, TB>>>(A0, Wr2, br2, out_reg);
    k_head101<<<GM, 512, HD_SMEM>>>(A1, Wc2, bc2, out_cls);
    k_head<1><<<GH, TB>>>(H1, Wo2, bo2, out_obj);
}

// round 13
// speedup vs baseline: 1.1275x; 1.1275x over previous
#include <cuda_runtime.h>
#include <cuda_bf16.h>

#define NN 65536
#define EE 1048576
#define DD 64
#define CC 101
#define BN_EPS 1e-5f

// ---------------- scratch (device globals; no allocation allowed) -------------
__device__ float g_Y0[NN * DD];        // single-tensor gather input
__device__ float g_Z [NN * 2 * DD];    // dual-tensor interleaved gather input
__device__ float g_A0[NN * DD];
__device__ float g_A1[NN * DD];
__device__ float g_H1[NN * DD];
__device__ float g_H2[NN * DD];
__device__ float g_H3[NN * DD];
__device__ int    g_cnt[NN];
__device__ int    g_ptr[NN + 1];
__device__ int    g_esrc[EE];
__device__ double g_stat[3][128];   // per-conv: [0:64) col sums, [64:128) col sumsq

// ---------------- CSR build --------------------------------------------------
__global__ void k_init() {
    int i = blockIdx.x * blockDim.x + threadIdx.x;
    if (i < NN) g_cnt[i] = 0;
    if (i < 3 * 128) ((double*)g_stat)[i] = 0.0;
}

__global__ void k_count(const int* __restrict__ dst) {
    int e = (blockIdx.x * blockDim.x + threadIdx.x) * 2;
    if (e < EE) {
        int2 d = *(const int2*)(dst + e);
        atomicAdd(&g_cnt[d.x], 1);
        atomicAdd(&g_cnt[d.y], 1);
    }
}

__global__ void k_scan() {
    __shared__ int ps[1024];
    int t = threadIdx.x;
    int base = t << 6;
    int s = 0;
#pragma unroll 8
    for (int j = 0; j < 64; j++) s += g_cnt[base + j];
    ps[t] = s;
    __syncthreads();
    for (int off = 1; off < 1024; off <<= 1) {
        int add = 0;
        if (t >= off) add = ps[t - off];
        __syncthreads();
        ps[t] += add;
        __syncthreads();
    }
    int incl = ps[t];
    int run = incl - s;
#pragma unroll 8
    for (int j = 0; j < 64; j++) {
        int c = g_cnt[base + j];
        g_ptr[base + j] = run;
        run += c;
        g_cnt[base + j] = 0;   // reuse as fill cursor in scatter
    }
    if (t == 1023) g_ptr[NN] = incl;
}

__global__ void k_scatter(const int* __restrict__ src, const int* __restrict__ dst) {
    int e = (blockIdx.x * blockDim.x + threadIdx.x) * 2;
    if (e < EE) {
        int2 d = *(const int2*)(dst + e);
        int2 s = *(const int2*)(src + e);
        int p0 = atomicAdd(&g_cnt[d.x], 1);
        g_esrc[g_ptr[d.x] + p0] = s.x;
        int p1 = atomicAdd(&g_cnt[d.y], 1);
        g_esrc[g_ptr[d.y] + p1] = s.y;
    }
}

// ---------------- register-tiled GEMM: 128 rows x 64 cols per block ----------
// 256 threads: tx = t&15 -> 4 cols, ty = t>>4 -> 8 rows. 32 outputs/thread.
// DUAL: two weight sets, one input tile, interleaved float4 output (Z layout:
// Z4[row*32 + 2tx+j] = {w0col(4tx+2j), w0col(4tx+2j+1), w1col(4tx+2j), w1col(4tx+2j+1)}).
// IN_BN: BN+ReLU applied to input on load (stats from g_stat[statIn] + gvec/bvec).
// STATS: accumulate column sum/sumsq of output0 into g_stat[statOut].
#define MM_AS_STRIDE 66
#define MM_SMEM_FLOATS (128 * MM_AS_STRIDE + 2 * 64 * 64 + 64 + 64 + 64 + 64)

template <int DUAL, int IN_BN, int STATS>
__global__ __launch_bounds__(256) void k_mm(
        const float* __restrict__ in,
        const float* __restrict__ W0, const float* __restrict__ W1,
        float* __restrict__ out0,
        const float* __restrict__ gvec, const float* __restrict__ bvec,
        int statIn, int statOut) {
    extern __shared__ float sm[];
    float* As  = sm;                          // 128 x 66
    float* Ws  = As + 128 * MM_AS_STRIDE;     // [2][64][64]
    float* bnS = Ws + 2 * 64 * 64;            // 64
    float* bnB = bnS + 64;                    // 64
    float* ssum = bnB + 64;                   // 64
    float* ssq  = ssum + 64;                  // 64

    int t = threadIdx.x;
    int tx = t & 15, ty = t >> 4;
    int row0 = blockIdx.x * 128;

    // weights
    for (int i = t; i < 4096; i += 256) {
        Ws[i] = W0[i];
        if (DUAL) Ws[4096 + i] = W1[i];
    }
    // BN scale/shift
    if (IN_BN && t < 64) {
        double sum = g_stat[statIn][t];
        double sq  = g_stat[statIn][64 + t];
        double mu_d = sum / (double)NN;
        double var_d = sq / (double)NN - mu_d * mu_d;
        float inv = rsqrtf(fmaxf((float)var_d, 0.f) + BN_EPS);
        float sc = inv * gvec[t];
        bnS[t] = sc;
        bnB[t] = bvec[t] - (float)mu_d * sc;
    }
    if (STATS && t < 64) { ssum[t] = 0.f; ssq[t] = 0.f; }
    if (IN_BN) __syncthreads();   // bnS/bnB ready before A-tile transform

    // A tile (128 x 64), optionally BN+ReLU on load
    {
        const float4* inr = (const float4*)(in + (size_t)row0 * 64);
#pragma unroll
        for (int i = 0; i < 8; i++) {
            int l = i * 256 + t;
            float4 v = inr[l];
            int r = l >> 4;
            int kk = (l & 15) * 4;
            if (IN_BN) {
                v.x = fmaxf(fmaf(v.x, bnS[kk + 0], bnB[kk + 0]), 0.f);
                v.y = fmaxf(fmaf(v.y, bnS[kk + 1], bnB[kk + 1]), 0.f);
                v.z = fmaxf(fmaf(v.z, bnS[kk + 2], bnB[kk + 2]), 0.f);
                v.w = fmaxf(fmaf(v.w, bnS[kk + 3], bnB[kk + 3]), 0.f);
            }
            float* d = As + r * MM_AS_STRIDE + kk;
            d[0] = v.x; d[1] = v.y; d[2] = v.z; d[3] = v.w;
        }
    }
    __syncthreads();

    float acc0[8][4];
    float acc1[8][4];
#pragma unroll
    for (int i = 0; i < 8; i++)
#pragma unroll
        for (int j = 0; j < 4; j++) { acc0[i][j] = 0.f; if (DUAL) acc1[i][j] = 0.f; }

    const float* arow = As + ty * 8 * MM_AS_STRIDE;
#pragma unroll 4
    for (int k = 0; k < 64; k++) {
        float4 w0 = *(const float4*)(Ws + k * 64 + tx * 4);
        float4 w1;
        if (DUAL) w1 = *(const float4*)(Ws + 4096 + k * 64 + tx * 4);
#pragma unroll
        for (int i = 0; i < 8; i++) {
            float a = arow[i * MM_AS_STRIDE + k];
            acc0[i][0] = fmaf(a, w0.x, acc0[i][0]);
            acc0[i][1] = fmaf(a, w0.y, acc0[i][1]);
            acc0[i][2] = fmaf(a, w0.z, acc0[i][2]);
            acc0[i][3] = fmaf(a, w0.w, acc0[i][3]);
            if (DUAL) {
                acc1[i][0] = fmaf(a, w1.x, acc1[i][0]);
                acc1[i][1] = fmaf(a, w1.y, acc1[i][1]);
                acc1[i][2] = fmaf(a, w1.z, acc1[i][2]);
                acc1[i][3] = fmaf(a, w1.w, acc1[i][3]);
            }
        }
    }

    // store
#pragma unroll
    for (int i = 0; i < 8; i++) {
        int row = row0 + ty * 8 + i;
        if (DUAL) {
            ((float4*)out0)[row * 32 + 2 * tx + 0] =
                make_float4(acc0[i][0], acc0[i][1], acc1[i][0], acc1[i][1]);
            ((float4*)out0)[row * 32 + 2 * tx + 1] =
                make_float4(acc0[i][2], acc0[i][3], acc1[i][2], acc1[i][3]);
        } else {
            ((float4*)out0)[row * 16 + tx] =
                make_float4(acc0[i][0], acc0[i][1], acc0[i][2], acc0[i][3]);
        }
    }

    if (STATS) {
        float cs[4] = {0.f, 0.f, 0.f, 0.f}, cq[4] = {0.f, 0.f, 0.f, 0.f};
#pragma unroll
        for (int i = 0; i < 8; i++)
#pragma unroll
            for (int j = 0; j < 4; j++) {
                float v = acc0[i][j];
                cs[j] += v;
                cq[j] += v * v;
            }
#pragma unroll
        for (int j = 0; j < 4; j++) {
            atomicAdd(&ssum[tx * 4 + j], cs[j]);
            atomicAdd(&ssq[tx * 4 + j], cq[j]);
        }
        __syncthreads();
        if (t < 64) {
            atomicAdd(&g_stat[statOut][t],      (double)ssum[t]);
            atomicAdd(&g_stat[statOut][64 + t], (double)ssq[t]);
        }
    }
}

// ---------------- gather-max: warp per node, shuffle-batched indices ---------
// A warp loads up to 32 contiguous edge indices with ONE coalesced lane-load,
// computes each lane's (dx,dy) once, then broadcasts (s,dx,dy) via shuffles.
// Inner loop = pure independent feature loads (no index->feature mem chain),
// unrolled x4 for MLP. HAS_S: float2/lane from Y. HAS_D: float4/lane from Z.
template <int HAS_S, int HAS_D>
__global__ __launch_bounds__(256) void k_gath(
        const float* __restrict__ yS, const float* __restrict__ zD,
        const float* __restrict__ pos,
        const float* __restrict__ WpS,   // pos-rows (2x64) of single Wl
        const float* __restrict__ WpD0, const float* __restrict__ WpD1,
        float* __restrict__ aS,
        float* __restrict__ aD0, float* __restrict__ aD1) {
    int t = threadIdx.x;
    int warp = t >> 5, lane = t & 31;
    int node = blockIdx.x * 8 + warp;

    const float2* YS = (const float2*)yS;
    const float4* ZD = (const float4*)zD;
    const float2* P  = (const float2*)pos;
    const unsigned FULL = 0xffffffffu;

    float2 wxS, wyS, wxD0, wyD0, wxD1, wyD1;
    if (HAS_S) {
        wxS = ((const float2*)WpS)[lane];
        wyS = ((const float2*)(WpS + 64))[lane];
    }
    if (HAS_D) {
        wxD0 = ((const float2*)WpD0)[lane];
        wyD0 = ((const float2*)(WpD0 + 64))[lane];
        wxD1 = ((const float2*)WpD1)[lane];
        wyD1 = ((const float2*)(WpD1 + 64))[lane];
    }

    float2 pi = P[node];
    float2 mS;
    float4 mD;
    if (HAS_S) mS = YS[node * 32 + lane];   // self-loop (dpos = 0)
    if (HAS_D) mD = ZD[node * 32 + lane];

    int b = g_ptr[node], e = g_ptr[node + 1];

    for (int base = b; base < e; base += 32) {
        int n = e - base;
        if (n > 32) n = 32;
        int ii = base + lane;
        int myIdx = g_esrc[ii < e ? ii : (e - 1)];   // coalesced batch index load
        float2 mp = P[myIdx];
        float dxl = mp.x - pi.x, dyl = mp.y - pi.y;

        int j = 0;
        for (; j + 4 <= n; j += 4) {
            int   s0 = __shfl_sync(FULL, myIdx, j + 0);
            float dx0 = __shfl_sync(FULL, dxl, j + 0);
            float dy0 = __shfl_sync(FULL, dyl, j + 0);
            int   s1 = __shfl_sync(FULL, myIdx, j + 1);
            float dx1 = __shfl_sync(FULL, dxl, j + 1);
            float dy1 = __shfl_sync(FULL, dyl, j + 1);
            int   s2 = __shfl_sync(FULL, myIdx, j + 2);
            float dx2 = __shfl_sync(FULL, dxl, j + 2);
            float dy2 = __shfl_sync(FULL, dyl, j + 2);
            int   s3 = __shfl_sync(FULL, myIdx, j + 3);
            float dx3 = __shfl_sync(FULL, dxl, j + 3);
            float dy3 = __shfl_sync(FULL, dyl, j + 3);

            if (HAS_S) {
                float2 v0 = YS[s0 * 32 + lane];
                float2 v1 = YS[s1 * 32 + lane];
                float2 v2 = YS[s2 * 32 + lane];
                float2 v3 = YS[s3 * 32 + lane];
                v0.x = fmaf(dx0, wxS.x, fmaf(dy0, wyS.x, v0.x));
                v0.y = fmaf(dx0, wxS.y, fmaf(dy0, wyS.y, v0.y));
                v1.x = fmaf(dx1, wxS.x, fmaf(dy1, wyS.x, v1.x));
                v1.y = fmaf(dx1, wxS.y, fmaf(dy1, wyS.y, v1.y));
                v2.x = fmaf(dx2, wxS.x, fmaf(dy2, wyS.x, v2.x));
                v2.y = fmaf(dx2, wxS.y, fmaf(dy2, wyS.y, v2.y));
                v3.x = fmaf(dx3, wxS.x, fmaf(dy3, wyS.x, v3.x));
                v3.y = fmaf(dx3, wxS.y, fmaf(dy3, wyS.y, v3.y));
                mS.x = fmaxf(mS.x, fmaxf(fmaxf(v0.x, v1.x), fmaxf(v2.x, v3.x)));
                mS.y = fmaxf(mS.y, fmaxf(fmaxf(v0.y, v1.y), fmaxf(v2.y, v3.y)));
            }
            if (HAS_D) {
                float4 u0 = ZD[s0 * 32 + lane];
                float4 u1 = ZD[s1 * 32 + lane];
                float4 u2 = ZD[s2 * 32 + lane];
                float4 u3 = ZD[s3 * 32 + lane];
                u0.x = fmaf(dx0, wxD0.x, fmaf(dy0, wyD0.x, u0.x));
                u0.y = fmaf(dx0, wxD0.y, fmaf(dy0, wyD0.y, u0.y));
                u0.z = fmaf(dx0, wxD1.x, fmaf(dy0, wyD1.x, u0.z));
                u0.w = fmaf(dx0, wxD1.y, fmaf(dy0, wyD1.y, u0.w));
                u1.x = fmaf(dx1, wxD0.x, fmaf(dy1, wyD0.x, u1.x));
                u1.y = fmaf(dx1, wxD0.y, fmaf(dy1, wyD0.y, u1.y));
                u1.z = fmaf(dx1, wxD1.x, fmaf(dy1, wyD1.x, u1.z));
                u1.w = fmaf(dx1, wxD1.y, fmaf(dy1, wyD1.y, u1.w));
                u2.x = fmaf(dx2, wxD0.x, fmaf(dy2, wyD0.x, u2.x));
                u2.y = fmaf(dx2, wxD0.y, fmaf(dy2, wyD0.y, u2.y));
                u2.z = fmaf(dx2, wxD1.x, fmaf(dy2, wyD1.x, u2.z));
                u2.w = fmaf(dx2, wxD1.y, fmaf(dy2, wyD1.y, u2.w));
                u3.x = fmaf(dx3, wxD0.x, fmaf(dy3, wyD0.x, u3.x));
                u3.y = fmaf(dx3, wxD0.y, fmaf(dy3, wyD0.y, u3.y));
                u3.z = fmaf(dx3, wxD1.x, fmaf(dy3, wyD1.x, u3.z));
                u3.w = fmaf(dx3, wxD1.y, fmaf(dy3, wyD1.y, u3.w));
                mD.x = fmaxf(mD.x, fmaxf(fmaxf(u0.x, u1.x), fmaxf(u2.x, u3.x)));
                mD.y = fmaxf(mD.y, fmaxf(fmaxf(u0.y, u1.y), fmaxf(u2.y, u3.y)));
                mD.z = fmaxf(mD.z, fmaxf(fmaxf(u0.z, u1.z), fmaxf(u2.z, u3.z)));
                mD.w = fmaxf(mD.w, fmaxf(fmaxf(u0.w, u1.w), fmaxf(u2.w, u3.w)));
            }
        }
        for (; j < n; j++) {
            int   s = __shfl_sync(FULL, myIdx, j);
            float dx = __shfl_sync(FULL, dxl, j);
            float dy = __shfl_sync(FULL, dyl, j);
            if (HAS_S) {
                float2 v = YS[s * 32 + lane];
                v.x = fmaf(dx, wxS.x, fmaf(dy, wyS.x, v.x));
                v.y = fmaf(dx, wxS.y, fmaf(dy, wyS.y, v.y));
                mS.x = fmaxf(mS.x, v.x);
                mS.y = fmaxf(mS.y, v.y);
            }
            if (HAS_D) {
                float4 u = ZD[s * 32 + lane];
                u.x = fmaf(dx, wxD0.x, fmaf(dy, wyD0.x, u.x));
                u.y = fmaf(dx, wxD0.y, fmaf(dy, wyD0.y, u.y));
                u.z = fmaf(dx, wxD1.x, fmaf(dy, wyD1.x, u.z));
                u.w = fmaf(dx, wxD1.y, fmaf(dy, wyD1.y, u.w));
                mD.x = fmaxf(mD.x, u.x);
                mD.y = fmaxf(mD.y, u.y);
                mD.z = fmaxf(mD.z, u.z);
                mD.w = fmaxf(mD.w, u.w);
            }
        }
    }

    if (HAS_S) ((float2*)aS)[node * 32 + lane] = mS;
    if (HAS_D) {
        ((float2*)aD0)[node * 32 + lane] = make_float2(mD.x, mD.y);
        ((float2*)aD1)[node * 32 + lane] = make_float2(mD.z, mD.w);
    }
}

// ---------------- cls head: 128 rows x 101 cols, register tiled --------------
#define HD_SMEM_FLOATS (128 * MM_AS_STRIDE + 64 * 128 + 128)

__global__ __launch_bounds__(512) void k_head101(
        const float* __restrict__ in, const float* __restrict__ W,
        const float* __restrict__ bias, float* __restrict__ out) {
    extern __shared__ float sm[];
    float* As = sm;                        // 128 x 66
    float* Ws = As + 128 * MM_AS_STRIDE;   // 64 x 128 (zero-padded)
    float* bS = Ws + 64 * 128;             // 128

    int t = threadIdx.x;
    int tx = t & 31, ty = t >> 5;
    int row0 = blockIdx.x * 128;

    for (int i = t; i < 64 * 128; i += 512) {
        int k = i >> 7, c = i & 127;
        Ws[i] = (c < CC) ? W[k * CC + c] : 0.f;
    }
    if (t < 128) bS[t] = (t < CC) ? bias[t] : 0.f;

    {
        const float4* inr = (const float4*)(in + (size_t)row0 * 64);
#pragma unroll
        for (int i = 0; i < 4; i++) {
            int l = i * 512 + t;
            float4 v = inr[l];
            int r = l >> 4;
            int kk = (l & 15) * 4;
            float* d = As + r * MM_AS_STRIDE + kk;
            d[0] = v.x; d[1] = v.y; d[2] = v.z; d[3] = v.w;
        }
    }
    __syncthreads();

    float acc[8][4];
#pragma unroll
    for (int i = 0; i < 8; i++)
#pragma unroll
        for (int j = 0; j < 4; j++) acc[i][j] = 0.f;

    const float* arow = As + ty * 8 * MM_AS_STRIDE;
#pragma unroll 4
    for (int k = 0; k < 64; k++) {
        float4 w = *(const float4*)(Ws + k * 128 + tx * 4);
#pragma unroll
        for (int i = 0; i < 8; i++) {
            float a = arow[i * MM_AS_STRIDE + k];
            acc[i][0] = fmaf(a, w.x, acc[i][0]);
            acc[i][1] = fmaf(a, w.y, acc[i][1]);
            acc[i][2] = fmaf(a, w.z, acc[i][2]);
            acc[i][3] = fmaf(a, w.w, acc[i][3]);
        }
    }

#pragma unroll
    for (int i = 0; i < 8; i++) {
        int row = row0 + ty * 8 + i;
#pragma unroll
        for (int j = 0; j < 4; j++) {
            int col = tx * 4 + j;
            if (col < CC) out[(size_t)row * CC + col] = acc[i][j] + bS[col];
        }
    }
}

// ---------------- small head GEMM (K = 4, 1): warp per row, shuffle ----------
template <int K>
__global__ void k_head(const float* __restrict__ in, const float* __restrict__ W,
                       const float* __restrict__ bias, float* __restrict__ out) {
    __shared__ float Ws[64 * K];
    int t = threadIdx.x;
    for (int i = t; i < 64 * K; i += blockDim.x) Ws[i] = W[i];
    __syncthreads();
    int warp = t >> 5, lane = t & 31;
    int row = blockIdx.x * 8 + warp;
    constexpr int NC = (K + 31) / 32;
    float acc[NC];
#pragma unroll
    for (int c = 0; c < NC; c++) {
        int col = lane + 32 * c;
        acc[c] = (col < K) ? bias[col] : 0.f;
    }
    float r0v = in[row * 64 + lane];
    float r1v = in[row * 64 + 32 + lane];
#pragma unroll
    for (int j = 0; j < 32; j++) {
        float v = __shfl_sync(0xffffffffu, r0v, j);
#pragma unroll
        for (int c = 0; c < NC; c++) {
            int col = lane + 32 * c;
            if (col < K) acc[c] = fmaf(v, Ws[j * K + col], acc[c]);
        }
    }
#pragma unroll
    for (int j = 0; j < 32; j++) {
        float v = __shfl_sync(0xffffffffu, r1v, j);
#pragma unroll
        for (int c = 0; c < NC; c++) {
            int col = lane + 32 * c;
            if (col < K) acc[c] = fmaf(v, Ws[(32 + j) * K + col], acc[c]);
        }
    }
#pragma unroll
    for (int c = 0; c < NC; c++) {
        int col = lane + 32 * c;
        if (col < K) out[row * K + col] = acc[c];
    }
}

// ---------------- launch -----------------------------------------------------
extern "C" void kernel_launch(void* const* d_in, const int* in_sizes, int n_in,
                              void* d_out, int out_size) {
    const float* x   = (const float*)d_in[0];
    const float* pos = (const float*)d_in[1];
    const int*   ei  = (const int*)  d_in[2];
    const float* W11 = (const float*)d_in[3];
    const float* W12 = (const float*)d_in[4];
    const float* g1  = (const float*)d_in[5];
    const float* b1  = (const float*)d_in[6];
    const float* W21 = (const float*)d_in[7];
    const float* W22 = (const float*)d_in[8];
    const float* g2  = (const float*)d_in[9];
    const float* b2  = (const float*)d_in[10];
    const float* W31 = (const float*)d_in[11];
    const float* W32 = (const float*)d_in[12];
    const float* g3  = (const float*)d_in[13];
    const float* b3  = (const float*)d_in[14];
    const float* Wr1 = (const float*)d_in[15];
    const float* Wr2 = (const float*)d_in[16];
    const float* br2 = (const float*)d_in[17];
    const float* Wc1 = (const float*)d_in[18];
    const float* Wc2 = (const float*)d_in[19];
    const float* bc2 = (const float*)d_in[20];
    const float* Wo1 = (const float*)d_in[21];
    const float* Wo2 = (const float*)d_in[22];
    const float* bo2 = (const float*)d_in[23];
    float* out = (float*)d_out;

    float* out_cls = out;                      // N x 101
    float* out_reg = out + (size_t)NN * CC;    // N x 4
    float* out_obj = out_reg + (size_t)NN * 4; // N x 1

    const int* src = ei;
    const int* dst = ei + EE;

    float *Y0, *Z, *A0, *A1, *H1, *H2, *H3;
    cudaGetSymbolAddress((void**)&Y0, g_Y0);
    cudaGetSymbolAddress((void**)&Z,  g_Z);
    cudaGetSymbolAddress((void**)&A0, g_A0);
    cudaGetSymbolAddress((void**)&A1, g_A1);
    cudaGetSymbolAddress((void**)&H1, g_H1);
    cudaGetSymbolAddress((void**)&H2, g_H2);
    cudaGetSymbolAddress((void**)&H3, g_H3);

    const int MM_SMEM = MM_SMEM_FLOATS * 4;
    const int HD_SMEM = HD_SMEM_FLOATS * 4;
    cudaFuncSetAttribute(k_mm<0, 0, 0>, cudaFuncAttributeMaxDynamicSharedMemorySize, MM_SMEM);
    cudaFuncSetAttribute(k_mm<0, 0, 1>, cudaFuncAttributeMaxDynamicSharedMemorySize, MM_SMEM);
    cudaFuncSetAttribute(k_mm<0, 1, 0>, cudaFuncAttributeMaxDynamicSharedMemorySize, MM_SMEM);
    cudaFuncSetAttribute(k_mm<1, 1, 0>, cudaFuncAttributeMaxDynamicSharedMemorySize, MM_SMEM);
    cudaFuncSetAttribute(k_head101,     cudaFuncAttributeMaxDynamicSharedMemorySize, HD_SMEM);

    const int TB = 256;

    // ---- CSR build
    k_init<<<(NN + TB - 1) / TB, TB>>>();
    k_count<<<EE / (2 * TB), TB>>>(dst);
    k_scan<<<1, 1024>>>();
    k_scatter<<<EE / (2 * TB), TB>>>(src, dst);

    const int GM = NN / 128;    // k_mm / k_head101 grid
    const int GA = NN / 8;      // gather grid (8 nodes/block, warp per node)
    const int GH = NN / 8;      // small-head grid

    // ---- conv1: x -> H1 (stats0)
    k_mm<0, 0, 0><<<GM, TB, MM_SMEM>>>(x, W11, nullptr, Y0, nullptr, nullptr, 0, 0);
    k_gath<1, 0><<<GA, TB>>>(Y0, nullptr, pos, W11 + 64 * 64, nullptr, nullptr,
                             A0, nullptr, nullptr);
    k_mm<0, 0, 1><<<GM, TB, MM_SMEM>>>(A0, W12, nullptr, H1, nullptr, nullptr, 0, 0);

    // ---- conv2 + conv3 lin from relu(bn1(H1)), dual interleaved -> Z
    k_mm<1, 1, 0><<<GM, TB, MM_SMEM>>>(H1, W21, W31, Z, g1, b1, 0, 0);
    k_gath<0, 1><<<GA, TB>>>(nullptr, Z, pos, nullptr, W21 + 64 * 64, W31 + 64 * 64,
                             nullptr, A0, A1);
    k_mm<0, 0, 1><<<GM, TB, MM_SMEM>>>(A0, W22, nullptr, H2, nullptr, nullptr, 0, 1);
    k_mm<0, 0, 1><<<GM, TB, MM_SMEM>>>(A1, W32, nullptr, H3, nullptr, nullptr, 0, 2);

    // ---- head pre-lins: reg from relu(bn2(H2)) -> Y0 ; cls+obj from relu(bn3(H3)) -> Z
    k_mm<0, 1, 0><<<GM, TB, MM_SMEM>>>(H2, Wr1, nullptr, Y0, g2, b2, 1, 0);
    k_mm<1, 1, 0><<<GM, TB, MM_SMEM>>>(H3, Wc1, Wo1, Z, g3, b3, 2, 0);

    // ---- single triple gather: reg (Y0) + cls/obj (Z)
    k_gath<1, 1><<<GA, TB>>>(Y0, Z, pos, Wr1 + 64 * 64, Wc1 + 64 * 64, Wo1 + 64 * 64,
                             A0, A1, H1);

    // ---- output heads
    k_head<4><<<GH, TB>>>(A0, Wr2, br2, out_reg);
    k_head101<<<GM, 512, HD_SMEM>>>(A1, Wc2, bc2, out_cls);
    k_head<1><<<GH, TB>>>(H1, Wo2, bo2, out_obj);
}